// round 9
// baseline (speedup 1.0000x reference)
#include <cuda_runtime.h>
#include <cuda_bf16.h>

#define S_DIM 128
#define A_DIM 96
#define B_DIM 256
#define LX    512
#define LY    256
#define XOFF_STRIDE 584   // padded clamped xs byte-offset table per batch

// g_Cn[s][a] = -softmax(P,axis=1)[s][a] - 1   (c'' for D'' space)
__device__ float g_Cn[S_DIM * A_DIM];
// Per-batch gathered cost table: Gt[b][x][j] = g_Cn[x][ys[b][j]]
__device__ float g_Gt[(size_t)B_DIM * S_DIM * LY];
// xoff[b][t] = xs[b][clamp(t-32, 0, xl-1)] * 1024  (byte row offset in Gt)
__device__ int   g_xoff[B_DIM * XOFF_STRIDE];

__global__ void softmax_neg_kernel(const float* __restrict__ P) {
    int row  = blockIdx.x;
    int lane = threadIdx.x;
    const float* pr = P + row * A_DIM;
    float v0 = pr[lane], v1 = pr[lane + 32], v2 = pr[lane + 64];
    float m = fmaxf(v0, fmaxf(v1, v2));
    #pragma unroll
    for (int o = 16; o > 0; o >>= 1) m = fmaxf(m, __shfl_xor_sync(0xffffffffu, m, o));
    float e0 = expf(v0 - m), e1 = expf(v1 - m), e2 = expf(v2 - m);
    float s = e0 + e1 + e2;
    #pragma unroll
    for (int o = 16; o > 0; o >>= 1) s += __shfl_xor_sync(0xffffffffu, s, o);
    float inv = -1.0f / s;
    g_Cn[row * A_DIM + lane     ] = e0 * inv - 1.0f;
    g_Cn[row * A_DIM + lane + 32] = e1 * inv - 1.0f;
    g_Cn[row * A_DIM + lane + 64] = e2 * inv - 1.0f;
}

// One block per batch: build Gt[b] (gather through smem) and xoff[b].
__global__ void build_kernel(const int* __restrict__ xs,
                             const int* __restrict__ ys,
                             const int* __restrict__ xlen) {
    __shared__ float sC[S_DIM * A_DIM];
    const int b   = blockIdx.x;
    const int tid = threadIdx.x;

    {   // stage cost table (12288 floats = 3072 float4)
        const float4* src = (const float4*)g_Cn;
        float4*       dst = (float4*)sC;
        #pragma unroll
        for (int i = tid; i < (S_DIM * A_DIM) / 4; i += 256) dst[i] = src[i];
    }

    const int xl   = xlen[b] - 1;
    const int xcap = xl - 1;
    const int* xsb = xs + (size_t)b * LX;
    for (int t = tid; t < XOFF_STRIDE; t += 256) {
        int q = t - 32;
        int v = min(max(q, 0), xcap);
        g_xoff[b * XOFF_STRIDE + t] = xsb[v] * (LY * 4);
    }
    __syncthreads();

    const int yj = ys[(size_t)b * LY + tid];
    float* ob = g_Gt + (size_t)b * S_DIM * LY + tid;
    #pragma unroll 4
    for (int x = 0; x < S_DIM; ++x)
        ob[x * LY] = sC[x * A_DIM + yj];
}

// One warp per batch, lane-skewed wavefront, D'' = D - j - r space.
//   E''[j]   = min(D''_{r-1}[j], D''_{r-1}[j-1] + c'')
//   D''_r[j] = min(prefixmin(E'')[j], B)        B = D''_r[8L] (shfl; lane0: 0)
// Serial prefix p (overlaps the shfl) + flat commit: boundary enters at
// depth 1, cross-lane cycle = SHFL+SEL+FMNMX. out = D'' + xl + yl.

#define DP_STEP(COMMIT) do {                                                   \
    /* prefetch costs for step s+4; xoff idx = (s+4)+31-lane */                \
    int xo_ = *xq; ++xq;                                                       \
    const char* rp_ = Gtb + xo_;                                               \
    float4 nA_ = *(const float4*)rp_;                                          \
    float4 nB_ = *(const float4*)(rp_ + 16);                                   \
    float Dl_eff = is0 ? 0.0f : Dl;                                            \
    float E0_ = fminf(D[0], bprev + cA[0].x);                                  \
    float E1_ = fminf(D[1], D[0] + cA[0].y);                                   \
    float E2_ = fminf(D[2], D[1] + cA[0].z);                                   \
    float E3_ = fminf(D[3], D[2] + cA[0].w);                                   \
    float E4_ = fminf(D[4], D[3] + cB[0].x);                                   \
    float E5_ = fminf(D[5], D[4] + cB[0].y);                                   \
    float E6_ = fminf(D[6], D[5] + cB[0].z);                                   \
    float E7_ = fminf(D[7], D[6] + cB[0].w);                                   \
    float p1_ = fminf(E0_, E1_);                                               \
    float p2_ = fminf(p1_, E2_);                                               \
    float p3_ = fminf(p2_, E3_);                                               \
    float p4_ = fminf(p3_, E4_);                                               \
    float p5_ = fminf(p4_, E5_);                                               \
    float p6_ = fminf(p5_, E6_);                                               \
    float p7_ = fminf(p6_, E7_);                                               \
    if (COMMIT) {                                                              \
        D[0] = fminf(E0_, Dl_eff);                                             \
        D[1] = fminf(p1_, Dl_eff);                                             \
        D[2] = fminf(p2_, Dl_eff);                                             \
        D[3] = fminf(p3_, Dl_eff);                                             \
        D[4] = fminf(p4_, Dl_eff);                                             \
        D[5] = fminf(p5_, Dl_eff);                                             \
        D[6] = fminf(p6_, Dl_eff);                                             \
        D[7] = fminf(p7_, Dl_eff);                                             \
    }                                                                          \
    float sh_ = __shfl_up_sync(0xffffffffu, D[7], 1);                          \
    bprev = Dl_eff;                                                            \
    Dl    = sh_;                                                               \
    cA[0] = cA[1]; cA[1] = cA[2]; cA[2] = cA[3]; cA[3] = nA_;                  \
    cB[0] = cB[1]; cB[1] = cB[2]; cB[2] = cB[3]; cB[3] = nB_;                  \
} while (0)

__global__ void __launch_bounds__(32, 4) dp_kernel(
    const int* __restrict__ xlen,
    const int* __restrict__ ylen,
    float* __restrict__ out)
{
    const int b    = blockIdx.x;
    const int lane = threadIdx.x;
    const int xl   = xlen[b] - 1;   // target row (1..511)
    const int yl   = ylen[b] - 1;   // target col (1..255)

    const char* Gtb = (const char*)(g_Gt + (size_t)b * S_DIM * LY) + lane * 32;
    const int*  xpb = g_xoff + b * XOFF_STRIDE;

    const int t_lane = (yl - 1) >> 3;
    const int k_t    = (yl - 1) & 7;
    const int s_end  = xl + t_lane;
    const bool is0   = (lane == 0);

    float D[8];
    #pragma unroll
    for (int k = 0; k < 8; ++k) D[k] = 0.0f;   // row 0: D'' = 0

    float Dl = 0.0f, bprev = 0.0f;

    // prefill cost pipeline: step sigma uses xoff idx sigma + 31 - lane
    float4 cA[4], cB[4];
    #pragma unroll
    for (int p = 0; p < 4; ++p) {
        int xv = xpb[32 - lane + p];            // steps 1..4
        const char* r = Gtb + xv;
        cA[p] = *(const float4*)r;
        cB[p] = *(const float4*)(r + 16);
    }
    const int* xq = xpb + 36 - lane;            // at step s: *xq = idx s+35-lane

    int s = 1;
    const int rampEnd = min(31, s_end);
    #pragma unroll 4
    for (; s <= rampEnd; ++s) {
        const bool act = (s > lane);
        DP_STEP(act);
    }
    #pragma unroll 4
    for (; s <= s_end; ++s) {
        DP_STEP(true);
    }

    if (lane == t_lane) out[b] = D[k_t] + (float)(xl + yl);
}

extern "C" void kernel_launch(void* const* d_in, const int* in_sizes, int n_in,
                              void* d_out, int out_size) {
    const float* P    = (const float*)d_in[0];
    const int*   xs   = (const int*)d_in[1];
    const int*   ys   = (const int*)d_in[2];
    const int*   xlen = (const int*)d_in[3];
    const int*   ylen = (const int*)d_in[4];
    float*       out  = (float*)d_out;

    softmax_neg_kernel<<<S_DIM, 32>>>(P);
    build_kernel<<<B_DIM, 256>>>(xs, ys, xlen);
    dp_kernel<<<B_DIM, 32>>>(xlen, ylen, out);
}

// round 10
// speedup vs baseline: 1.2488x; 1.2488x over previous
#include <cuda_runtime.h>
#include <cuda_bf16.h>

#define S_DIM 128
#define A_DIM 96
#define B_DIM 256
#define LX    512
#define LY    256
#define XOFF_STRIDE 584   // padded clamped xs byte-offset table per batch

// g_Cn[s][a] = -softmax(P,axis=1)[s][a] - 1   (c'' for D'' space)
__device__ float g_Cn[S_DIM * A_DIM];
// Per-batch gathered cost table: Gt[b][x][j] = g_Cn[x][ys[b][j]]
__device__ float g_Gt[(size_t)B_DIM * S_DIM * LY];
// xoff[b][t] = xs[b][clamp(t-32, 0, xl-1)] * 1024  (byte row offset in Gt)
__device__ int   g_xoff[B_DIM * XOFF_STRIDE];

__global__ void softmax_neg_kernel(const float* __restrict__ P) {
    int row  = blockIdx.x;
    int lane = threadIdx.x;
    const float* pr = P + row * A_DIM;
    float v0 = pr[lane], v1 = pr[lane + 32], v2 = pr[lane + 64];
    float m = fmaxf(v0, fmaxf(v1, v2));
    #pragma unroll
    for (int o = 16; o > 0; o >>= 1) m = fmaxf(m, __shfl_xor_sync(0xffffffffu, m, o));
    float e0 = expf(v0 - m), e1 = expf(v1 - m), e2 = expf(v2 - m);
    float s = e0 + e1 + e2;
    #pragma unroll
    for (int o = 16; o > 0; o >>= 1) s += __shfl_xor_sync(0xffffffffu, s, o);
    float inv = -1.0f / s;
    g_Cn[row * A_DIM + lane     ] = e0 * inv - 1.0f;
    g_Cn[row * A_DIM + lane + 32] = e1 * inv - 1.0f;
    g_Cn[row * A_DIM + lane + 64] = e2 * inv - 1.0f;
}

// One block per batch: build Gt[b] (gather through smem) and xoff[b].
__global__ void build_kernel(const int* __restrict__ xs,
                             const int* __restrict__ ys,
                             const int* __restrict__ xlen) {
    __shared__ float sC[S_DIM * A_DIM];
    const int b   = blockIdx.x;
    const int tid = threadIdx.x;

    {   // stage cost table (12288 floats = 3072 float4)
        const float4* src = (const float4*)g_Cn;
        float4*       dst = (float4*)sC;
        #pragma unroll
        for (int i = tid; i < (S_DIM * A_DIM) / 4; i += 256) dst[i] = src[i];
    }

    const int xl   = xlen[b] - 1;
    const int xcap = xl - 1;
    const int* xsb = xs + (size_t)b * LX;
    for (int t = tid; t < XOFF_STRIDE; t += 256) {
        int q = t - 32;
        int v = min(max(q, 0), xcap);
        g_xoff[b * XOFF_STRIDE + t] = xsb[v] * (LY * 4);
    }
    __syncthreads();

    const int yj = ys[(size_t)b * LY + tid];
    float* ob = g_Gt + (size_t)b * S_DIM * LY + tid;
    #pragma unroll 4
    for (int x = 0; x < S_DIM; ++x)
        ob[x * LY] = sC[x * A_DIM + yj];
}

// One warp per batch, lane-skewed wavefront, D'' = D - j - r space (R7 math).
//   E''[j]   = min(D''_{r-1}[j], D''_{r-1}[j-1] + c'')
//   D''_r[j] = min(KSprefixmin(E'')[j], B)     B = D''_r[8L] (shfl; lane0: 0)
// Steady loop is hand-modulo-scheduled x4: phase p consumes buffer slot p and
// refills slot p for step s+4 -> zero rotation MOVs in the hot path.

// shared core: consumes cost (a,bv), prefetches into slot (NA,NB) from xo_
#define DP_CORE(a, bv, NA, NB, xo_, COMMIT) do {                               \
    const char* rp_ = Gtb + (xo_);                                             \
    float4 nA_ = *(const float4*)rp_;                                          \
    float4 nB_ = *(const float4*)(rp_ + 16);                                   \
    float Dl_eff = is0 ? 0.0f : Dl;                                            \
    float E0_ = fminf(D[0], bprev + (a).x);                                    \
    float E1_ = fminf(D[1], D[0] + (a).y);                                     \
    float E2_ = fminf(D[2], D[1] + (a).z);                                     \
    float E3_ = fminf(D[3], D[2] + (a).w);                                     \
    float E4_ = fminf(D[4], D[3] + (bv).x);                                    \
    float E5_ = fminf(D[5], D[4] + (bv).y);                                    \
    float E6_ = fminf(D[6], D[5] + (bv).z);                                    \
    float E7_ = fminf(D[7], D[6] + (bv).w);                                    \
    float t10_ = E0_;                                                          \
    float t11_ = fminf(E1_, E0_);                                              \
    float t12_ = fminf(E2_, E1_);                                              \
    float t13_ = fminf(E3_, E2_);                                              \
    float t14_ = fminf(E4_, E3_);                                              \
    float t15_ = fminf(E5_, E4_);                                              \
    float t16_ = fminf(E6_, E5_);                                              \
    float t17_ = fminf(E7_, E6_);                                              \
    float t20_ = t10_;                                                         \
    float t21_ = t11_;                                                         \
    float t22_ = fminf(t12_, t10_);                                            \
    float t23_ = fminf(t13_, t11_);                                            \
    float t24_ = fminf(t14_, t12_);                                            \
    float t25_ = fminf(t15_, t13_);                                            \
    float t26_ = fminf(t16_, t14_);                                            \
    float t27_ = fminf(t17_, t15_);                                            \
    if (COMMIT) {                                                              \
        D[0] = fminf(t20_, Dl_eff);                                            \
        D[1] = fminf(t21_, Dl_eff);                                            \
        D[2] = fminf(t22_, Dl_eff);                                            \
        D[3] = fminf(t23_, Dl_eff);                                            \
        D[4] = fminf(fminf(t24_, t20_), Dl_eff);                               \
        D[5] = fminf(fminf(t25_, t21_), Dl_eff);                               \
        D[6] = fminf(fminf(t26_, t22_), Dl_eff);                               \
        D[7] = fminf(fminf(t27_, t23_), Dl_eff);                               \
    }                                                                          \
    float sh_ = __shfl_up_sync(0xffffffffu, D[7], 1);                          \
    bprev = Dl_eff;                                                            \
    Dl    = sh_;                                                               \
    (NA) = nA_;  (NB) = nB_;                                                   \
} while (0)

// rotating variant (ramp + remainder): consume slot 0, rotate, refill slot 3
#define DP_STEP_ROT(COMMIT) do {                                               \
    int xor_ = xo[0];                                                          \
    float4 rA_, rB_;                                                           \
    DP_CORE(cA[0], cB[0], rA_, rB_, xor_, COMMIT);                             \
    cA[0] = cA[1]; cA[1] = cA[2]; cA[2] = cA[3]; cA[3] = rA_;                  \
    cB[0] = cB[1]; cB[1] = cB[2]; cB[2] = cB[3]; cB[3] = rB_;                  \
    xo[0] = xo[1]; xo[1] = xo[2]; xo[2] = xo[3]; xo[3] = *xpr; ++xpr;          \
} while (0)

// phase variant (steady): literal slot p, zero rotations
#define DP_STEP_PH(p) do {                                                     \
    DP_CORE(cA[p], cB[p], cA[p], cB[p], xo[p], true);                          \
    xo[p] = xpr[p];                                                            \
} while (0)

__global__ void __launch_bounds__(32, 4) dp_kernel(
    const int* __restrict__ xlen,
    const int* __restrict__ ylen,
    float* __restrict__ out)
{
    const int b    = blockIdx.x;
    const int lane = threadIdx.x;
    const int xl   = xlen[b] - 1;   // target row (1..511)
    const int yl   = ylen[b] - 1;   // target col (1..255)

    const char* Gtb = (const char*)(g_Gt + (size_t)b * S_DIM * LY) + lane * 32;
    const int*  xpb = g_xoff + b * XOFF_STRIDE;

    const int t_lane = (yl - 1) >> 3;
    const int k_t    = (yl - 1) & 7;
    const int s_end  = xl + t_lane;
    const bool is0   = (lane == 0);

    float D[8];
    #pragma unroll
    for (int k = 0; k < 8; ++k) D[k] = 0.0f;   // row 0: D'' = 0

    float Dl = 0.0f, bprev = 0.0f;

    // prefill: step sigma uses xoff idx sigma + 31 - lane
    float4 cA[4], cB[4];
    #pragma unroll
    for (int p = 0; p < 4; ++p) {
        int xv = xpb[32 - lane + p];            // steps 1..4
        const char* r = Gtb + xv;
        cA[p] = *(const float4*)r;
        cB[p] = *(const float4*)(r + 16);
    }
    int xo[4];
    #pragma unroll
    for (int p = 0; p < 4; ++p) xo[p] = xpb[36 - lane + p];   // steps 5..8
    const int* xpr = xpb + 40 - lane;           // steps 9.. (prefetch feed)

    // ---- ramp-in: freeze predicate live, rotating buffers ----
    int s = 1;
    const int rampEnd = min(31, s_end);
    for (; s <= rampEnd; ++s) {
        const bool act = (s > lane);
        DP_STEP_ROT(act);
    }

    // ---- steady: hand-unrolled x4, literal phases, no rotations ----
    int nSteady = s_end - s + 1;
    int n4      = nSteady & ~3;
    const int* xq_end = xpr + n4;
    for (; xpr != xq_end; xpr += 4) {
        DP_STEP_PH(0);
        DP_STEP_PH(1);
        DP_STEP_PH(2);
        DP_STEP_PH(3);
    }
    s += n4;

    // ---- remainder (<=3 steps), rotating ----
    for (; s <= s_end; ++s) {
        DP_STEP_ROT(true);
    }

    if (lane == t_lane) out[b] = D[k_t] + (float)(xl + yl);
}

extern "C" void kernel_launch(void* const* d_in, const int* in_sizes, int n_in,
                              void* d_out, int out_size) {
    const float* P    = (const float*)d_in[0];
    const int*   xs   = (const int*)d_in[1];
    const int*   ys   = (const int*)d_in[2];
    const int*   xlen = (const int*)d_in[3];
    const int*   ylen = (const int*)d_in[4];
    float*       out  = (float*)d_out;

    softmax_neg_kernel<<<S_DIM, 32>>>(P);
    build_kernel<<<B_DIM, 256>>>(xs, ys, xlen);
    dp_kernel<<<B_DIM, 32>>>(xlen, ylen, out);
}